// round 11
// baseline (speedup 1.0000x reference)
#include <cuda_runtime.h>
#include <cstdint>

// Problem constants
#define Bn 4
#define Cn 256
#define Hn 128
#define Wn 224
#define HW (Hn*Wn)
#define PD 4
#define NDISP 9

// Tiling: 8x32 outputs per CTA, each thread 8 px, 9 dy warps, 1 CTA/SM
#define TH 8
#define TW 32
#define PX 8
#define CC 16                // channels per stage
#define NK (Cn / CC)         // 16 stages
#define SROWS (TH + 2*PD)    // 16
#define SREAL (TW + 2*PD)    // 40 real cols
#define SCOLS 44             // padded: 11 granules/row, 11 mod 8 = 3 -> conflict-free
#define FCOLS 36             // 32 real + 4 pad: 9 granules, conflict-free
#define NTHREADS 288         // 9 dy warps x (8 rows x 4 col-groups of 8 px)

#define S_STAGE (CC * SROWS * SCOLS)   // 11264 floats
#define F_STAGE (CC * TH * FCOLS)      // 4608 floats
#define S_BYTES (S_STAGE * 4)
#define F_BYTES (F_STAGE * 4)
#define SMEM_BYTES (2 * (S_BYTES + F_BYTES))   // 126976 B -> 1 CTA/SM

#define CSTEP_B (CC * HW * 4)          // gmem byte advance per stage

#define NSROW (CC * SROWS)             // 256 second row-slots (10 chunks each)
#define NFROW (CC * TH)                // 128 first row-slots (8 chunks each)

typedef unsigned long long ull;

__device__ __forceinline__ uint32_t saddr(const void* p) {
    return (uint32_t)__cvta_generic_to_shared(p);
}
__device__ __forceinline__ void cpa16(uint32_t dst, const float* src, int sz) {
    asm volatile("cp.async.cg.shared.global [%0], [%1], 16, %2;\n"
                 :: "r"(dst), "l"(src), "r"(sz));
}
#define CP_COMMIT() asm volatile("cp.async.commit_group;\n" ::: "memory")
#define CP_WAIT0()  asm volatile("cp.async.wait_group 0;\n" ::: "memory")

// (hi word of a, lo word of b) -> packed pair (w_{2k+1}, w_{2k+2})
__device__ __forceinline__ ull mk(ull a, ull b) {
    ull r;
    asm("mov.b64 %0, {%1, %2};" : "=l"(r)
        : "r"((uint32_t)(a >> 32)), "r"((uint32_t)b));
    return r;
}
#define FMA2(a, x, y) asm("fma.rn.f32x2 %0, %1, %2, %0;" : "+l"(a) : "l"(x), "l"(y))
#define UNPACK2(l0, h0, s) asm("mov.b64 {%0, %1}, %2;" : "=f"(l0), "=f"(h0) : "l"(s))

__global__ void __launch_bounds__(NTHREADS, 1)
corr_kernel(const float* __restrict__ first, const float* __restrict__ second,
            float* __restrict__ out)
{
    extern __shared__ float sm[];
    float* sS = sm;                      // [2][CC][SROWS][SCOLS]
    float* fS = sm + 2 * S_STAGE;        // [2][CC][TH][FCOLS]

    const int tid = threadIdx.x;
    const int x0g = blockIdx.x * TW;
    const int y0  = blockIdx.y * TH;
    const int b   = blockIdx.z;

    const float* fbase = first  + (size_t)b * Cn * HW;
    const float* sbase = second + (size_t)b * Cn * HW;

    const uint32_t smemS = saddr(sS);
    const uint32_t smemF = saddr(fS);

    // ---- row-based loader slots (computed ONCE) ----
    // second: 256 row-slots (tid < 256), 10 chunks of 16B each
    long   sgo = 0;      // gmem byte offset of chunk 0 (may be negative at left edge)
    uint32_t sso = 0;    // smem byte offset of chunk 0
    uint32_t smask = 0;  // bit k: chunk k in-bounds
    if (tid < NSROW) {
        int c   = tid >> 4;        // /16
        int row = tid & 15;
        int gy  = y0 - PD + row;
        bool rowok = ((unsigned)gy < (unsigned)Hn);
        sgo = ((long)(c * Hn + (rowok ? gy : 0)) * Wn + (x0g - PD)) * 4;
        sso = (uint32_t)(((c * SROWS + row) * SCOLS) * 4);
        if (rowok) {
            #pragma unroll
            for (int k = 0; k < 10; k++) {
                int gx = x0g - PD + 4 * k;
                if (gx >= 0 && gx + 3 < Wn) smask |= (1u << k);
            }
        }
    }
    // first: 128 row-slots (tid < 128), 8 chunks each, always in-bounds
    long fgo = 0; uint32_t fso = 0;
    const bool hasF = (tid < NFROW);
    if (hasF) {
        int c   = tid >> 3;
        int row = tid & 7;
        fgo = ((long)(c * Hn + (y0 + row)) * Wn + x0g) * 4;
        fso = (uint32_t)(((c * TH + row) * FCOLS) * 4);
    }

    #define ISSUE(buf) do {                                                          \
        if (tid < NSROW) {                                                           \
            uint32_t d_ = smemS + (buf) * S_BYTES + sso;                             \
            const char* g_ = (const char*)sbase + sgo;                               \
            _Pragma("unroll")                                                        \
            for (int k = 0; k < 10; k++)                                             \
                cpa16(d_ + 16u * k, (const float*)(g_ + 16 * k),                     \
                      ((smask >> k) & 1u) ? 16 : 0);                                 \
            sgo += CSTEP_B;                                                          \
        }                                                                            \
        if (hasF) {                                                                  \
            uint32_t d_ = smemF + (buf) * F_BYTES + fso;                             \
            const char* g_ = (const char*)fbase + fgo;                               \
            _Pragma("unroll")                                                        \
            for (int k = 0; k < 8; k++)                                              \
                cpa16(d_ + 16u * k, (const float*)(g_ + 16 * k), 16);                \
            fgo += CSTEP_B;                                                          \
        }                                                                            \
        CP_COMMIT();                                                                 \
    } while (0)

    // ---- compute mapping: g = dy (warp-uniform) ----
    const int g   = tid >> 5;              // 0..8 (= dy)
    const int pid = tid & 31;
    const int py  = pid & 7;               // row 0..7
    const int xo  = ((pid >> 3) & 3) * PX; // 0,8,16,24

    // 36 packed accumulators = 72 fp32: [dx][pixel-pair 0..3]
    ull acc[NDISP][4];
    #pragma unroll
    for (int dx = 0; dx < NDISP; dx++)
        #pragma unroll
        for (int p = 0; p < 4; p++) acc[dx][p] = 0ull;

    ISSUE(0);

    const int srow_off = (py + g) * SCOLS + xo;
    const int frow_off = py * FCOLS + xo;

    #pragma unroll 1
    for (int kc = 0; kc < NK; kc++) {
        CP_WAIT0();
        __syncthreads();                 // everyone done reading the other buffer
        if (kc + 1 < NK) ISSUE((kc + 1) & 1);

        const float* sC = sS + (kc & 1) * S_STAGE + srow_off;
        const float* fC = fS + (kc & 1) * F_STAGE + frow_off;

        // ---- software-pipelined channel loop: load c+1 while FMAing c ----
        ulonglong2 A, B, C2, D, F0, F1;
        A  = *(const ulonglong2*)(sC);
        B  = *(const ulonglong2*)(sC + 4);
        C2 = *(const ulonglong2*)(sC + 8);
        D  = *(const ulonglong2*)(sC + 12);
        F0 = *(const ulonglong2*)(fC);
        F1 = *(const ulonglong2*)(fC + 4);

        #pragma unroll
        for (int c = 0; c < CC; c++) {
            // consume current into locals (SSA — renamed, no real movs)
            ull q0 = A.x,  q1 = A.y,  q2 = B.x,  q3 = B.y;
            ull q4 = C2.x, q5 = C2.y, q6 = D.x,  q7 = D.y;
            ull f0 = F0.x, f1 = F0.y, f2 = F1.x, f3 = F1.y;

            // prefetch next channel during this channel's math
            if (c + 1 < CC) {
                const float* sn = sC + (c + 1) * (SROWS * SCOLS);
                const float* fn = fC + (c + 1) * (TH * FCOLS);
                A  = *(const ulonglong2*)(sn);
                B  = *(const ulonglong2*)(sn + 4);
                C2 = *(const ulonglong2*)(sn + 8);
                D  = *(const ulonglong2*)(sn + 12);
                F0 = *(const ulonglong2*)(fn);
                F1 = *(const ulonglong2*)(fn + 4);
            }

            // pairs pr[i] = (w_i, w_{i+1}); even free, 7 odd via packs
            ull pr[15];
            pr[0]  = q0;  pr[2]  = q1;  pr[4]  = q2;  pr[6]  = q3;
            pr[8]  = q4;  pr[10] = q5;  pr[12] = q6;  pr[14] = q7;
            pr[1]  = mk(q0, q1);  pr[3]  = mk(q1, q2);
            pr[5]  = mk(q2, q3);  pr[7]  = mk(q3, q4);
            pr[9]  = mk(q4, q5);  pr[11] = mk(q5, q6);
            pr[13] = mk(q6, q7);

            #pragma unroll
            for (int dx = 0; dx < NDISP; dx++) {
                FMA2(acc[dx][0], f0, pr[dx]);
                FMA2(acc[dx][1], f1, pr[dx + 2]);
                FMA2(acc[dx][2], f2, pr[dx + 4]);
                FMA2(acc[dx][3], f3, pr[dx + 6]);
            }
        }
    }

    // ---- epilogue: scale and store 8 px per dx ----
    const float inv = 1.0f / (float)Cn;
    #pragma unroll
    for (int dx = 0; dx < NDISP; dx++) {
        float a0, a1, a2, a3, a4, a5, a6, a7;
        UNPACK2(a0, a1, acc[dx][0]);
        UNPACK2(a2, a3, acc[dx][1]);
        UNPACK2(a4, a5, acc[dx][2]);
        UNPACK2(a6, a7, acc[dx][3]);
        int d = g * NDISP + dx;
        float* dst = out + (((size_t)b * (NDISP * NDISP) + d) * HW)
                     + (y0 + py) * Wn + x0g + xo;
        *(float4*)(dst)     = make_float4(a0 * inv, a1 * inv, a2 * inv, a3 * inv);
        *(float4*)(dst + 4) = make_float4(a4 * inv, a5 * inv, a6 * inv, a7 * inv);
    }
}

extern "C" void kernel_launch(void* const* d_in, const int* in_sizes, int n_in,
                              void* d_out, int out_size)
{
    const float* first  = (const float*)d_in[0];
    const float* second = (const float*)d_in[1];
    float* out = (float*)d_out;

    cudaFuncSetAttribute(corr_kernel, cudaFuncAttributeMaxDynamicSharedMemorySize, SMEM_BYTES);

    dim3 grid(Wn / TW, Hn / TH, Bn);   // 7 x 16 x 4 = 448 blocks
    corr_kernel<<<grid, NTHREADS, SMEM_BYTES>>>(first, second, out);
}

// round 13
// speedup vs baseline: 1.1234x; 1.1234x over previous
#include <cuda_runtime.h>
#include <cstdint>

// Problem constants
#define Bn 4
#define Cn 256
#define Hn 128
#define Wn 224
#define HW (Hn*Wn)
#define PD 4
#define NDISP 9

// Tiling: 8x16 outputs per CTA, each thread 4 px, 9 dy warps, 2 CTAs/SM
#define TH 8
#define TW 16
#define PX 4
#define CC 16                // channels per stage
#define NK (Cn / CC)         // 16 stages
#define SROWS (TH + 2*PD)    // 16
#define SREAL (TW + 2*PD)    // 24 real cols -> 6 16B chunks
#define SCOLS 28             // padded: 7 granules/row, conflict-free walk
#define FCOLS 20             // 16 real + 4 pad
#define NTHREADS 288         // 9 dy warps x (8 rows x 4 col-groups of 4 px)

#define S_STAGE (CC * SROWS * SCOLS)   // 7168 floats
#define F_STAGE (CC * TH * FCOLS)      // 2560 floats
#define S_BYTES (S_STAGE * 4)          // 28672
#define F_BYTES (F_STAGE * 4)          // 10240
#define SMEM_BYTES (2 * (S_BYTES + F_BYTES))   // 77824 B -> 2 CTAs/SM

#define CSTEP_B (CC * HW * 4)          // gmem byte advance per stage

#define NSROW (CC * SROWS)             // 256 second row-slots (6 chunks each)
#define NFROW (CC * TH)                // 128 first row-slots (4 chunks each)

typedef unsigned long long ull;

__device__ __forceinline__ uint32_t saddr(const void* p) {
    return (uint32_t)__cvta_generic_to_shared(p);
}
__device__ __forceinline__ void cpa16(uint32_t dst, const float* src, int sz) {
    asm volatile("cp.async.cg.shared.global [%0], [%1], 16, %2;\n"
                 :: "r"(dst), "l"(src), "r"(sz));
}
#define CP_COMMIT() asm volatile("cp.async.commit_group;\n" ::: "memory")
#define CP_WAIT0()  asm volatile("cp.async.wait_group 0;\n" ::: "memory")

// (hi word of a, lo word of b) -> packed pair (w_{2k+1}, w_{2k+2})
__device__ __forceinline__ ull mk(ull a, ull b) {
    ull r;
    asm("mov.b64 %0, {%1, %2};" : "=l"(r)
        : "r"((uint32_t)(a >> 32)), "r"((uint32_t)b));
    return r;
}
#define FMA2(a, x, y) asm("fma.rn.f32x2 %0, %1, %2, %0;" : "+l"(a) : "l"(x), "l"(y))
#define UNPACK2(l0, h0, s) asm("mov.b64 {%0, %1}, %2;" : "=f"(l0), "=f"(h0) : "l"(s))

__global__ void __launch_bounds__(NTHREADS, 2)
corr_kernel(const float* __restrict__ first, const float* __restrict__ second,
            float* __restrict__ out)
{
    extern __shared__ float sm[];
    float* sS = sm;                      // [2][CC][SROWS][SCOLS]
    float* fS = sm + 2 * S_STAGE;        // [2][CC][TH][FCOLS]

    const int tid = threadIdx.x;
    const int x0g = blockIdx.x * TW;
    const int y0  = blockIdx.y * TH;
    const int b   = blockIdx.z;

    const float* fbase = first  + (size_t)b * Cn * HW;
    const float* sbase = second + (size_t)b * Cn * HW;

    const uint32_t smemS = saddr(sS);
    const uint32_t smemF = saddr(fS);

    // ---- row-based loader slots (computed ONCE) ----
    // second: 256 row-slots (tid < 256), 6 chunks of 16B each
    int      sgo = 0;    // gmem byte offset of chunk 0 (may be negative at left edge)
    uint32_t sso = 0;    // smem byte offset of chunk 0
    uint32_t smask = 0;  // bit k: chunk k in-bounds
    if (tid < NSROW) {
        int c   = tid >> 4;
        int row = tid & 15;
        int gy  = y0 - PD + row;
        bool rowok = ((unsigned)gy < (unsigned)Hn);
        sgo = ((c * Hn + (rowok ? gy : 0)) * Wn + (x0g - PD)) * 4;
        sso = (uint32_t)(((c * SROWS + row) * SCOLS) * 4);
        if (rowok) {
            #pragma unroll
            for (int k = 0; k < 6; k++) {
                int gx = x0g - PD + 4 * k;
                if (gx >= 0 && gx + 3 < Wn) smask |= (1u << k);
            }
        }
    }
    // first: 128 row-slots (tid < 128), 4 chunks each, always in-bounds
    int fgo = 0; uint32_t fso = 0;
    const bool hasF = (tid < NFROW);
    if (hasF) {
        int c   = tid >> 3;
        int row = tid & 7;
        fgo = ((c * Hn + (y0 + row)) * Wn + x0g) * 4;
        fso = (uint32_t)(((c * TH + row) * FCOLS) * 4);
    }

    #define ISSUE(buf) do {                                                          \
        if (tid < NSROW) {                                                           \
            uint32_t d_ = smemS + (buf) * S_BYTES + sso;                             \
            const char* g_ = (const char*)sbase + sgo;                               \
            _Pragma("unroll")                                                        \
            for (int k = 0; k < 6; k++)                                              \
                cpa16(d_ + 16u * k, (const float*)(g_ + 16 * k),                     \
                      ((smask >> k) & 1u) ? 16 : 0);                                 \
            sgo += CSTEP_B;                                                          \
        }                                                                            \
        if (hasF) {                                                                  \
            uint32_t d_ = smemF + (buf) * F_BYTES + fso;                             \
            const char* g_ = (const char*)fbase + fgo;                               \
            _Pragma("unroll")                                                        \
            for (int k = 0; k < 4; k++)                                              \
                cpa16(d_ + 16u * k, (const float*)(g_ + 16 * k), 16);                \
            fgo += CSTEP_B;                                                          \
        }                                                                            \
        CP_COMMIT();                                                                 \
    } while (0)

    // ---- compute mapping: g = dy (warp-uniform) ----
    const int g   = tid >> 5;              // 0..8 (= dy)
    const int pid = tid & 31;
    const int py  = pid & 7;               // row 0..7
    const int xo  = ((pid >> 3) & 3) * PX; // 0,4,8,12

    // 18 packed accumulators = 36 fp32: [dx][pixel-pair]
    ull acc[NDISP][2];
    #pragma unroll
    for (int dx = 0; dx < NDISP; dx++) { acc[dx][0] = 0ull; acc[dx][1] = 0ull; }

    ISSUE(0);

    const int srow_off = (py + g) * SCOLS + xo;
    const int frow_off = py * FCOLS + xo;

    #pragma unroll 1
    for (int kc = 0; kc < NK; kc++) {
        CP_WAIT0();
        __syncthreads();                 // all threads done reading the other buffer
        if (kc + 1 < NK) ISSUE((kc + 1) & 1);

        const float* sC = sS + (kc & 1) * S_STAGE + srow_off;
        const float* fC = fS + (kc & 1) * F_STAGE + frow_off;

        #pragma unroll
        for (int c = 0; c < CC; c++) {
            // first: 4 px -> 2 free f32x2 pairs
            const ulonglong2 fq = *(const ulonglong2*)(fC + c * (TH * FCOLS));
            ull f2a = fq.x, f2b = fq.y;

            // second window: 12 floats -> 6 free even pairs
            const float* sp = sC + c * (SROWS * SCOLS);
            const ulonglong2 A  = *(const ulonglong2*)(sp);
            const ulonglong2 B  = *(const ulonglong2*)(sp + 4);
            const ulonglong2 C2 = *(const ulonglong2*)(sp + 8);
            ull q0 = A.x, q1 = A.y, q2 = B.x, q3 = B.y, q4 = C2.x, q5 = C2.y;

            ull pr1 = mk(q0, q1);
            ull pr3 = mk(q1, q2);
            ull pr5 = mk(q2, q3);
            ull pr7 = mk(q3, q4);
            ull pr9 = mk(q4, q5);

            ull pr[11] = {q0, pr1, q1, pr3, q2, pr5, q3, pr7, q4, pr9, q5};

            #pragma unroll
            for (int dx = 0; dx < NDISP; dx++) {
                FMA2(acc[dx][0], f2a, pr[dx]);       // pixels xo, xo+1
                FMA2(acc[dx][1], f2b, pr[dx + 2]);   // pixels xo+2, xo+3
            }
        }
    }

    // ---- epilogue: scale and store 4 px per dx ----
    const float inv = 1.0f / (float)Cn;
    #pragma unroll
    for (int dx = 0; dx < NDISP; dx++) {
        float l0, h0, l1, h1;
        UNPACK2(l0, h0, acc[dx][0]);
        UNPACK2(l1, h1, acc[dx][1]);
        int d = g * NDISP + dx;
        float* dst = out + (((size_t)b * (NDISP * NDISP) + d) * HW)
                     + (y0 + py) * Wn + x0g + xo;
        *(float4*)dst = make_float4(l0 * inv, h0 * inv, l1 * inv, h1 * inv);
    }
}

extern "C" void kernel_launch(void* const* d_in, const int* in_sizes, int n_in,
                              void* d_out, int out_size)
{
    const float* first  = (const float*)d_in[0];
    const float* second = (const float*)d_in[1];
    float* out = (float*)d_out;

    cudaFuncSetAttribute(corr_kernel, cudaFuncAttributeMaxDynamicSharedMemorySize, SMEM_BYTES);

    dim3 grid(Wn / TW, Hn / TH, Bn);   // 14 x 16 x 4 = 896 blocks
    corr_kernel<<<grid, NTHREADS, SMEM_BYTES>>>(first, second, out);
}

// round 14
// speedup vs baseline: 1.3155x; 1.1710x over previous
#include <cuda_runtime.h>
#include <cstdint>

// Problem constants
#define Bn 4
#define Cn 256
#define Hn 128
#define Wn 224
#define HW (Hn*Wn)
#define PD 4
#define NDISP 9

// Tiling (R6 geometry): 8x16 outputs, PX=4, 9 dy warps, 2 CTAs/SM, triple-buffered
#define TH 8
#define TW 16
#define PX 4
#define CC 8                 // channels per stage
#define NK (Cn / CC)         // 32 stages
#define SROWS (TH + 2*PD)    // 16
#define SREAL (TW + 2*PD)    // 24 real cols
#define SCOLS 28             // padded, conflict-free
#define FCOLS 20             // 16 real + 4 pad
#define NTHREADS 288         // 9 dy warps x 32

#define S_STAGE (CC * SROWS * SCOLS)   // 3584 floats
#define F_STAGE (CC * TH * FCOLS)      // 1280 floats
#define S_BYTES (S_STAGE * 4)
#define F_BYTES (F_STAGE * 4)
#define NBUF 3
#define SMEM_BYTES (NBUF * (S_BYTES + F_BYTES))   // 58368 B -> 2 CTAs/SM

#define CSTEP (CC * HW)                 // gmem float advance per stage

#define NSLOT_S (CC * SROWS * (SREAL/4))   // 768 16B chunks
#define NSLOT_F (CC * TH * (TW/4))         // 256 chunks

typedef unsigned long long ull;

__device__ __forceinline__ uint32_t saddr(const void* p) {
    return (uint32_t)__cvta_generic_to_shared(p);
}
__device__ __forceinline__ void cpa16(uint32_t dst, const float* src, int sz) {
    asm volatile("cp.async.cg.shared.global [%0], [%1], 16, %2;\n"
                 :: "r"(dst), "l"(src), "r"(sz));
}
#define CP_COMMIT() asm volatile("cp.async.commit_group;\n" ::: "memory")
#define CP_WAIT1()  asm volatile("cp.async.wait_group 1;\n" ::: "memory")
#define CP_WAIT0()  asm volatile("cp.async.wait_group 0;\n" ::: "memory")

// (hi word of a, lo word of b) -> packed pair (w_{2k+1}, w_{2k+2})
__device__ __forceinline__ ull mk(ull a, ull b) {
    ull r;
    asm("mov.b64 %0, {%1, %2};" : "=l"(r)
        : "r"((uint32_t)(a >> 32)), "r"((uint32_t)b));
    return r;
}
#define FMA2(a, x, y) asm("fma.rn.f32x2 %0, %1, %2, %0;" : "+l"(a) : "l"(x), "l"(y))
#define UNPACK2(l0, h0, s) asm("mov.b64 {%0, %1}, %2;" : "=f"(l0), "=f"(h0) : "l"(s))

__global__ void __launch_bounds__(NTHREADS, 2)
corr_kernel(const float* __restrict__ first, const float* __restrict__ second,
            float* __restrict__ out)
{
    extern __shared__ float sm[];
    float* sS = sm;                       // [NBUF][CC][SROWS][SCOLS]
    float* fS = sm + NBUF * S_STAGE;      // [NBUF][CC][TH][FCOLS]

    const int tid = threadIdx.x;
    const int x0g = blockIdx.x * TW;
    const int y0  = blockIdx.y * TH;
    const int b   = blockIdx.z;

    const float* fbase = first  + (size_t)b * Cn * HW;
    const float* sbase = second + (size_t)b * Cn * HW;

    const uint32_t smemS = saddr(sS);
    const uint32_t smemF = saddr(fS);

    // ---- precompute loader slots ONCE (R6 coalesced chunk-interleaved mapping) ----
    const float* gp[3]; uint32_t so[3]; int sz[3];
    #pragma unroll
    for (int k = 0; k < 3; k++) {
        int s = tid + k * NTHREADS;
        if (s < NSLOT_S) {
            int c   = s / (SROWS * (SREAL/4));
            int rem = s - c * (SROWS * (SREAL/4));
            int row = rem / (SREAL/4);
            int j   = (rem - row * (SREAL/4)) * 4;
            int gy  = y0 - PD + row;
            int gx  = x0g - PD + j;
            bool ok = ((unsigned)gy < (unsigned)Hn) && ((unsigned)gx < (unsigned)Wn);
            gp[k] = sbase + ((size_t)c * Hn + (ok ? gy : 0)) * Wn + (ok ? gx : 0);
            so[k] = ((c * SROWS + row) * SCOLS + j) * 4;
            sz[k] = ok ? 16 : 0;
        } else {
            gp[k] = sbase; so[k] = 0; sz[k] = -1;
        }
    }
    const float* gpF = fbase; uint32_t soF = 0;
    const bool hasF = (tid < NSLOT_F);
    if (hasF) {
        int c   = tid >> 5;
        int rem = tid & 31;
        int row = rem >> 2;
        int j   = (rem & 3) * 4;
        gpF = fbase + ((size_t)c * Hn + (y0 + row)) * Wn + (x0g + j);
        soF = ((c * TH + row) * FCOLS + j) * 4;
    }

    #define ISSUE(buf) do {                                                        \
        uint32_t sb_ = smemS + (buf) * S_BYTES;                                    \
        if (sz[0] >= 0) { cpa16(sb_ + so[0], gp[0], sz[0]); gp[0] += CSTEP; }      \
        if (sz[1] >= 0) { cpa16(sb_ + so[1], gp[1], sz[1]); gp[1] += CSTEP; }      \
        if (sz[2] >= 0) { cpa16(sb_ + so[2], gp[2], sz[2]); gp[2] += CSTEP; }      \
        if (hasF) { cpa16(smemF + (buf) * F_BYTES + soF, gpF, 16); gpF += CSTEP; } \
        CP_COMMIT();                                                               \
    } while (0)

    // ---- compute mapping: g = dy (warp-uniform) ----
    const int g   = tid >> 5;              // 0..8 (= dy)
    const int pid = tid & 31;
    const int py  = pid & 7;               // row 0..7
    const int xo  = ((pid >> 3) & 3) * PX; // 0,4,8,12

    // 18 packed accumulators = 36 fp32: [dx][pixel-pair]
    ull acc[NDISP][2];
    #pragma unroll
    for (int dx = 0; dx < NDISP; dx++) { acc[dx][0] = 0ull; acc[dx][1] = 0ull; }

    ISSUE(0);
    ISSUE(1);

    const int srow_off = (py + g) * SCOLS + xo;
    const int frow_off = py * FCOLS + xo;

    // buffer index kc % 3, tracked incrementally
    int cur = 0, nxt2 = 2;

    #pragma unroll 1
    for (int kc = 0; kc < NK; kc++) {
        if (kc + 1 < NK) CP_WAIT1();     // group kc complete (kc+1 may be pending)
        else             CP_WAIT0();
        __syncthreads();                 // readers of buffer nxt2 (iter kc-1) are done
        if (kc + 2 < NK) ISSUE(nxt2);    // safe: after the sync

        const float* sC = sS + cur * S_STAGE + srow_off;
        const float* fC = fS + cur * F_STAGE + frow_off;

        #pragma unroll
        for (int c = 0; c < CC; c++) {
            // first: 4 px -> 2 free f32x2 pairs
            const ulonglong2 fq = *(const ulonglong2*)(fC + c * (TH * FCOLS));
            ull f2a = fq.x, f2b = fq.y;

            // second window: 12 floats -> 6 free even pairs
            const float* sp = sC + c * (SROWS * SCOLS);
            const ulonglong2 A  = *(const ulonglong2*)(sp);
            const ulonglong2 B  = *(const ulonglong2*)(sp + 4);
            const ulonglong2 C2 = *(const ulonglong2*)(sp + 8);
            ull q0 = A.x, q1 = A.y, q2 = B.x, q3 = B.y, q4 = C2.x, q5 = C2.y;

            ull pr1 = mk(q0, q1);
            ull pr3 = mk(q1, q2);
            ull pr5 = mk(q2, q3);
            ull pr7 = mk(q3, q4);
            ull pr9 = mk(q4, q5);

            ull pr[11] = {q0, pr1, q1, pr3, q2, pr5, q3, pr7, q4, pr9, q5};

            #pragma unroll
            for (int dx = 0; dx < NDISP; dx++) {
                FMA2(acc[dx][0], f2a, pr[dx]);       // pixels xo, xo+1
                FMA2(acc[dx][1], f2b, pr[dx + 2]);   // pixels xo+2, xo+3
            }
        }

        cur  = (cur  == NBUF - 1) ? 0 : cur + 1;
        nxt2 = (nxt2 == NBUF - 1) ? 0 : nxt2 + 1;
    }

    // ---- epilogue: scale and store 4 px per dx ----
    const float inv = 1.0f / (float)Cn;
    #pragma unroll
    for (int dx = 0; dx < NDISP; dx++) {
        float l0, h0, l1, h1;
        UNPACK2(l0, h0, acc[dx][0]);
        UNPACK2(l1, h1, acc[dx][1]);
        int d = g * NDISP + dx;
        float* dst = out + (((size_t)b * (NDISP * NDISP) + d) * HW)
                     + (y0 + py) * Wn + x0g + xo;
        *(float4*)dst = make_float4(l0 * inv, h0 * inv, l1 * inv, h1 * inv);
    }
}

extern "C" void kernel_launch(void* const* d_in, const int* in_sizes, int n_in,
                              void* d_out, int out_size)
{
    const float* first  = (const float*)d_in[0];
    const float* second = (const float*)d_in[1];
    float* out = (float*)d_out;

    cudaFuncSetAttribute(corr_kernel, cudaFuncAttributeMaxDynamicSharedMemorySize, SMEM_BYTES);

    dim3 grid(Wn / TW, Hn / TH, Bn);   // 14 x 16 x 4 = 896 blocks
    corr_kernel<<<grid, NTHREADS, SMEM_BYTES>>>(first, second, out);
}

// round 15
// speedup vs baseline: 1.3944x; 1.0600x over previous
#include <cuda_runtime.h>
#include <cstdint>

// Problem constants
#define Bn 4
#define Cn 256
#define Hn 128
#define Wn 224
#define HW (Hn*Wn)
#define PD 4
#define NDISP 9

// Tiling: 8x32 outputs per CTA, PX=4, dy=3 per thread, 192 threads, 2 CTAs/SM
#define TH 8
#define TW 32
#define PX 4
#define DY 3                  // dy per thread
#define CC 8                  // channels per stage
#define NK (Cn / CC)          // 32 stages
#define SROWS (TH + 2*PD)     // 16
#define SREAL (TW + 2*PD)     // 40 real cols -> 10 chunks
#define SCOLS 44              // padded: 176B stride, conflict-free
#define FCOLS 36              // 32 real + 4 pad: 144B stride, conflict-free
#define NTHREADS 192          // 3 dy-groups x (8 rows x 8 col-groups of 4 px)

#define S_STAGE (CC * SROWS * SCOLS)   // 5632 floats
#define F_STAGE (CC * TH * FCOLS)      // 2304 floats
#define S_BYTES (S_STAGE * 4)
#define F_BYTES (F_STAGE * 4)
#define NBUF 3
#define SMEM_BYTES (NBUF * (S_BYTES + F_BYTES))   // 95232 B -> 2 CTAs/SM

#define CSTEP_B (CC * HW * 4)          // gmem byte advance per stage

#define NSLOT_S (CC * SROWS * (SREAL/4))   // 1280 chunks
#define NSLOT_F (CC * TH * (TW/4))         // 512 chunks
#define KS 7                                // ceil(1280/192): k<6 full, k=6 tid<128
#define KF 3                                // ceil(512/192):  k<2 full, k=2 tid<128

typedef unsigned long long ull;

__device__ __forceinline__ uint32_t saddr(const void* p) {
    return (uint32_t)__cvta_generic_to_shared(p);
}
__device__ __forceinline__ void cpa16(uint32_t dst, const float* src, int sz) {
    asm volatile("cp.async.cg.shared.global [%0], [%1], 16, %2;\n"
                 :: "r"(dst), "l"(src), "r"(sz));
}
#define CP_COMMIT() asm volatile("cp.async.commit_group;\n" ::: "memory")
#define CP_WAIT1()  asm volatile("cp.async.wait_group 1;\n" ::: "memory")
#define CP_WAIT0()  asm volatile("cp.async.wait_group 0;\n" ::: "memory")

// (hi word of a, lo word of b) -> packed pair (w_{2k+1}, w_{2k+2})
__device__ __forceinline__ ull mk(ull a, ull b) {
    ull r;
    asm("mov.b64 %0, {%1, %2};" : "=l"(r)
        : "r"((uint32_t)(a >> 32)), "r"((uint32_t)b));
    return r;
}
#define FMA2(a, x, y) asm("fma.rn.f32x2 %0, %1, %2, %0;" : "+l"(a) : "l"(x), "l"(y))
#define UNPACK2(l0, h0, s) asm("mov.b64 {%0, %1}, %2;" : "=f"(l0), "=f"(h0) : "l"(s))

__global__ void __launch_bounds__(NTHREADS, 2)
corr_kernel(const float* __restrict__ first, const float* __restrict__ second,
            float* __restrict__ out)
{
    extern __shared__ float sm[];
    float* sS = sm;                       // [NBUF][CC][SROWS][SCOLS]
    float* fS = sm + NBUF * S_STAGE;      // [NBUF][CC][TH][FCOLS]

    const int tid = threadIdx.x;
    const int x0g = blockIdx.x * TW;
    const int y0  = blockIdx.y * TH;
    const int b   = blockIdx.z;

    const float* fbase = first  + (size_t)b * Cn * HW;
    const float* sbase = second + (size_t)b * Cn * HW;

    const uint32_t smemS = saddr(sS);
    const uint32_t smemF = saddr(fS);

    // ---- precompute loader slots ONCE (coalesced chunk-interleaved, u32 offsets) ----
    uint32_t sgo[KS], sso[KS];           // gmem/smem byte offsets
    int      ssz[KS];                    // 16 in-bounds, 0 halo-zero
    #pragma unroll
    for (int k = 0; k < KS; k++) {
        int s = tid + k * NTHREADS;
        if (s < NSLOT_S) {
            int c   = s / (SROWS * (SREAL/4));
            int rem = s - c * (SROWS * (SREAL/4));
            int row = rem / (SREAL/4);
            int j   = (rem - row * (SREAL/4)) * 4;
            int gy  = y0 - PD + row;
            int gx  = x0g - PD + j;
            bool ok = ((unsigned)gy < (unsigned)Hn) && (gx >= 0) && (gx + 4 <= Wn);
            sgo[k] = ok ? (uint32_t)(((c * Hn + gy) * Wn + gx) * 4) : 0u;
            sso[k] = (uint32_t)(((c * SROWS + row) * SCOLS + j) * 4);
            ssz[k] = ok ? 16 : 0;
        } else { sgo[k] = 0; sso[k] = 0; ssz[k] = 0; }
    }
    uint32_t fgo[KF], fso[KF];
    #pragma unroll
    for (int k = 0; k < KF; k++) {
        int s = tid + k * NTHREADS;
        if (s < NSLOT_F) {
            int c   = s >> 6;                // / 64
            int rem = s & 63;
            int row = rem >> 3;
            int j   = (rem & 7) * 4;
            fgo[k] = (uint32_t)(((c * Hn + (y0 + row)) * Wn + (x0g + j)) * 4);
            fso[k] = (uint32_t)(((c * TH + row) * FCOLS + j) * 4);
        } else { fgo[k] = 0; fso[k] = 0; }
    }
    const bool sTail = (tid < NSLOT_S - 6 * NTHREADS);   // k=6 active (tid<128)
    const bool fTail = (tid < NSLOT_F - 2 * NTHREADS);   // k=2 active (tid<128)

    #define ISSUE(buf) do {                                                         \
        uint32_t sb_ = smemS + (buf) * S_BYTES;                                     \
        uint32_t fb_ = smemF + (buf) * F_BYTES;                                     \
        _Pragma("unroll")                                                           \
        for (int k = 0; k < KS - 1; k++) {                                          \
            cpa16(sb_ + sso[k], (const float*)((const char*)sbase + sgo[k]), ssz[k]); \
            sgo[k] += CSTEP_B;                                                      \
        }                                                                           \
        if (sTail) {                                                                \
            cpa16(sb_ + sso[KS-1], (const float*)((const char*)sbase + sgo[KS-1]), ssz[KS-1]); \
            sgo[KS-1] += CSTEP_B;                                                   \
        }                                                                           \
        _Pragma("unroll")                                                           \
        for (int k = 0; k < KF - 1; k++) {                                          \
            cpa16(fb_ + fso[k], (const float*)((const char*)fbase + fgo[k]), 16);   \
            fgo[k] += CSTEP_B;                                                      \
        }                                                                           \
        if (fTail) {                                                                \
            cpa16(fb_ + fso[KF-1], (const float*)((const char*)fbase + fgo[KF-1]), 16); \
            fgo[KF-1] += CSTEP_B;                                                   \
        }                                                                           \
        CP_COMMIT();                                                                \
    } while (0)

    // ---- compute mapping: g = dy-group (uniform per 64-thread pair of warps) ----
    const int g   = tid >> 6;              // 0..2 -> dy in {3g, 3g+1, 3g+2}
    const int pid = tid & 63;
    const int py  = pid & 7;               // row 0..7
    const int xo  = ((pid >> 3) & 7) * PX; // 0,4,...,28

    // 54 packed accumulators = 108 fp32: [r][dx][pixel-pair]
    ull acc[DY][NDISP][2];
    #pragma unroll
    for (int r = 0; r < DY; r++)
        #pragma unroll
        for (int dx = 0; dx < NDISP; dx++) { acc[r][dx][0] = 0ull; acc[r][dx][1] = 0ull; }

    ISSUE(0);
    ISSUE(1);

    const int srow_off = (py + DY * g) * SCOLS + xo;   // row for r=0
    const int frow_off = py * FCOLS + xo;

    int cur = 0, nxt2 = 2;

    #pragma unroll 1
    for (int kc = 0; kc < NK; kc++) {
        if (kc + 1 < NK) CP_WAIT1();
        else             CP_WAIT0();
        __syncthreads();                 // readers of buffer nxt2 (iter kc-1) done
        if (kc + 2 < NK) ISSUE(nxt2);

        const float* sC = sS + cur * S_STAGE + srow_off;
        const float* fC = fS + cur * F_STAGE + frow_off;

        #pragma unroll
        for (int c = 0; c < CC; c++) {
            // first: 4 px -> 2 free f32x2 pairs, REUSED across 3 dy
            const ulonglong2 fq = *(const ulonglong2*)(fC + c * (TH * FCOLS));
            const ull f2a = fq.x, f2b = fq.y;

            #pragma unroll
            for (int r = 0; r < DY; r++) {
                // second row (py + 3g + r): 12 floats -> 6 free even pairs
                const float* sp = sC + c * (SROWS * SCOLS) + r * SCOLS;
                const ulonglong2 A  = *(const ulonglong2*)(sp);
                const ulonglong2 B  = *(const ulonglong2*)(sp + 4);
                const ulonglong2 C2 = *(const ulonglong2*)(sp + 8);
                ull q0 = A.x, q1 = A.y, q2 = B.x, q3 = B.y, q4 = C2.x, q5 = C2.y;

                ull pr1 = mk(q0, q1);
                ull pr3 = mk(q1, q2);
                ull pr5 = mk(q2, q3);
                ull pr7 = mk(q3, q4);
                ull pr9 = mk(q4, q5);

                ull pr[11] = {q0, pr1, q1, pr3, q2, pr5, q3, pr7, q4, pr9, q5};

                #pragma unroll
                for (int dx = 0; dx < NDISP; dx++) {
                    FMA2(acc[r][dx][0], f2a, pr[dx]);       // pixels xo, xo+1
                    FMA2(acc[r][dx][1], f2b, pr[dx + 2]);   // pixels xo+2, xo+3
                }
            }
        }

        cur  = (cur  == NBUF - 1) ? 0 : cur + 1;
        nxt2 = (nxt2 == NBUF - 1) ? 0 : nxt2 + 1;
    }

    // ---- epilogue: scale and store 4 px per (r,dx) ----
    const float inv = 1.0f / (float)Cn;
    #pragma unroll
    for (int r = 0; r < DY; r++) {
        #pragma unroll
        for (int dx = 0; dx < NDISP; dx++) {
            float l0, h0, l1, h1;
            UNPACK2(l0, h0, acc[r][dx][0]);
            UNPACK2(l1, h1, acc[r][dx][1]);
            int d = (DY * g + r) * NDISP + dx;
            float* dst = out + (((size_t)b * (NDISP * NDISP) + d) * HW)
                         + (y0 + py) * Wn + x0g + xo;
            *(float4*)dst = make_float4(l0 * inv, h0 * inv, l1 * inv, h1 * inv);
        }
    }
}

extern "C" void kernel_launch(void* const* d_in, const int* in_sizes, int n_in,
                              void* d_out, int out_size)
{
    const float* first  = (const float*)d_in[0];
    const float* second = (const float*)d_in[1];
    float* out = (float*)d_out;

    cudaFuncSetAttribute(corr_kernel, cudaFuncAttributeMaxDynamicSharedMemorySize, SMEM_BYTES);

    dim3 grid(Wn / TW, Hn / TH, Bn);   // 7 x 16 x 4 = 448 blocks
    corr_kernel<<<grid, NTHREADS, SMEM_BYTES>>>(first, second, out);
}